// round 2
// baseline (speedup 1.0000x reference)
#include <cuda_runtime.h>
#include <cuda_bf16.h>
#include <math.h>

#define NMAX   100000
#define EMAX   1600000
#define FH     64

// Scratch (alloc-free rule: __device__ globals)
__device__ float g_A[NMAX * FH];      // gather source h'
__device__ float g_B[NMAX * FH];      // scatter accumulator
__device__ float g_deg[NMAX];
__device__ float g_dinv[NMAX];
__device__ int2  g_edges[EMAX];
__device__ int   g_is64;

// ---------------------------------------------------------------------------
// f32x2 packed-math helpers (FFMA2 only reachable via PTX)
#define PACK2(d, x, y) asm("mov.b64 %0,{%1,%2};" : "=l"(d) : "f"(x), "f"(y))
#define DUP2(d, x)     asm("mov.b64 %0,{%1,%1};" : "=l"(d) : "f"(x))
#define FMA2(c, a, b)  asm("fma.rn.f32x2 %0,%1,%2,%0;" : "+l"(c) : "l"(a), "l"(b))
#define UNPK(lo, hi, s) asm("mov.b64 {%0,%1},%2;" : "=f"(lo), "=f"(hi) : "l"(s))

// ---------------------------------------------------------------------------
// Detect int64 vs int32 edge_index (values < 100000 -> all int64 high words 0)
__global__ void probe_dtype(const long long* __restrict__ ei) {
    __shared__ int any;
    if (threadIdx.x == 0) any = 0;
    __syncthreads();
    for (int i = threadIdx.x; i < 1024; i += blockDim.x) {
        long long v = ei[i];
        if ((v >> 32) != 0) any = 1;
    }
    __syncthreads();
    if (threadIdx.x == 0) g_is64 = (any == 0) ? 1 : 0;
}

__global__ void init_deg(int n) {
    int i = blockIdx.x * blockDim.x + threadIdx.x;
    if (i < n) g_deg[i] = 1.0f;            // self-loop
}

// Convert edges to packed int2 + accumulate degree
__global__ void convert_deg(const void* __restrict__ ei, int E) {
    int e = blockIdx.x * blockDim.x + threadIdx.x;
    if (e >= E) return;
    int s, d;
    if (g_is64) {
        const long long* p = (const long long*)ei;
        s = (int)p[e]; d = (int)p[E + e];
    } else {
        const int* p = (const int*)ei;
        s = p[e]; d = p[E + e];
    }
    g_edges[e] = make_int2(s, d);
    atomicAdd(&g_deg[d], 1.0f);
}

__global__ void dinv_kernel(int n) {
    int i = blockIdx.x * blockDim.x + threadIdx.x;
    if (i < n) {
        float dg = g_deg[i];
        g_dinv[i] = (dg > 0.f) ? rsqrtf(dg) : 0.f;
    }
}

// ---------------------------------------------------------------------------
// Scatter: B[d,:] += A[s,:]   (normalization already folded into A and the
// consumer's load transform). 16 lanes per edge, float4 RED.
__global__ void scatter_kernel(const float* __restrict__ A, float* __restrict__ B, int E) {
    int g = blockIdx.x * blockDim.x + threadIdx.x;
    int lane = g & 15;
    int e = g >> 4;
    if (e >= E) return;
    int2 ed = g_edges[e];
    float4 v = ((const float4*)(A + (size_t)ed.x * FH))[lane];
    atomicAdd(((float4*)(B + (size_t)ed.y * FH)) + lane, v);
}

// ---------------------------------------------------------------------------
// FFMA2 GEMM: O = f(X) @ W with optional load transform and epilogue.
// TRANS:  x_load = relu(dinv[row]*x + bin[col])       (consumes aggregated B)
// FC==0:  epilogue v *= dinv[row]; dual-write O1, O2  (h' + accumulator init)
// FC==1:  epilogue v += bout[col]; single write O1
// Block: 256 threads; tile BM x N; thread tile 8 rows x 8 cols (f32x2 pairs
// along rows). Xs stored transposed [k][row] so a-pairs come from LDS.128.
template<int K, int N, bool TRANS, bool FC>
__global__ void __launch_bounds__(256)
gemm_f32x2(const float* __restrict__ X, const float* __restrict__ W,
           const float* __restrict__ bin, const float* __restrict__ bout,
           float* __restrict__ O1, float* __restrict__ O2, int n)
{
    constexpr int CT = N / 8;          // threads along cols
    constexpr int RT = 256 / CT;       // threads along rows
    constexpr int BM = RT * 8;         // 256 (N=64) or 512 (N=32)
    constexpr int BK = 16;
    __shared__ float Xs[BK][BM + 4];   // transposed: [k][row]
    __shared__ float Ws[BK][N];

    int tid = threadIdx.x;
    int tx = tid % CT;
    int ty = tid / CT;
    int row0 = blockIdx.x * BM;

    unsigned long long acc[4][8];
    #pragma unroll
    for (int p = 0; p < 4; p++)
        #pragma unroll
        for (int j = 0; j < 8; j++) acc[p][j] = 0ull;

    for (int k0 = 0; k0 < K; k0 += BK) {
        // X tile: BM rows x BK cols, float4 global loads, transposed store
        #pragma unroll
        for (int i = 0; i < BM / 64; i++) {
            int idx = tid + i * 256;
            int r  = idx >> 2;         // 4 float4 per row (BK=16)
            int c4 = idx & 3;
            int row = row0 + r;
            float4 v = make_float4(0.f, 0.f, 0.f, 0.f);
            if (row < n) {
                v = *(const float4*)(X + (size_t)row * K + k0 + c4 * 4);
                if (TRANS) {
                    float s = g_dinv[row];
                    v.x = fmaxf(fmaf(v.x, s, bin[k0 + c4*4 + 0]), 0.f);
                    v.y = fmaxf(fmaf(v.y, s, bin[k0 + c4*4 + 1]), 0.f);
                    v.z = fmaxf(fmaf(v.z, s, bin[k0 + c4*4 + 2]), 0.f);
                    v.w = fmaxf(fmaf(v.w, s, bin[k0 + c4*4 + 3]), 0.f);
                }
            }
            Xs[c4*4 + 0][r] = v.x;
            Xs[c4*4 + 1][r] = v.y;
            Xs[c4*4 + 2][r] = v.z;
            Xs[c4*4 + 3][r] = v.w;
        }
        // W tile: BK x N
        if (tid < 4 * N) {
            int r  = tid / (N / 4);
            int c4 = tid % (N / 4);
            *(float4*)&Ws[r][c4*4] = *(const float4*)(W + (size_t)(k0 + r) * N + c4*4);
        }
        __syncthreads();

        #pragma unroll
        for (int k = 0; k < BK; k++) {
            float4 a03 = *(const float4*)&Xs[k][ty*8];
            float4 a47 = *(const float4*)&Xs[k][ty*8 + 4];
            float4 w03 = *(const float4*)&Ws[k][tx*8];
            float4 w47 = *(const float4*)&Ws[k][tx*8 + 4];
            unsigned long long ap0, ap1, ap2, ap3, wd[8];
            PACK2(ap0, a03.x, a03.y); PACK2(ap1, a03.z, a03.w);
            PACK2(ap2, a47.x, a47.y); PACK2(ap3, a47.z, a47.w);
            DUP2(wd[0], w03.x); DUP2(wd[1], w03.y);
            DUP2(wd[2], w03.z); DUP2(wd[3], w03.w);
            DUP2(wd[4], w47.x); DUP2(wd[5], w47.y);
            DUP2(wd[6], w47.z); DUP2(wd[7], w47.w);
            #pragma unroll
            for (int j = 0; j < 8; j++) {
                FMA2(acc[0][j], ap0, wd[j]);
                FMA2(acc[1][j], ap1, wd[j]);
                FMA2(acc[2][j], ap2, wd[j]);
                FMA2(acc[3][j], ap3, wd[j]);
            }
        }
        __syncthreads();
    }

    // Epilogue
    #pragma unroll
    for (int p = 0; p < 4; p++) {
        #pragma unroll
        for (int h = 0; h < 2; h++) {
            int row = row0 + ty*8 + 2*p + h;
            if (row >= n) continue;
            float v[8];
            #pragma unroll
            for (int j = 0; j < 8; j++) {
                float lo, hi;
                UNPK(lo, hi, acc[p][j]);
                v[j] = h ? hi : lo;
            }
            if (FC) {
                float4 o0, o1;
                o0.x = v[0] + bout[tx*8 + 0];
                o0.y = v[1] + bout[tx*8 + 1];
                o0.z = v[2] + bout[tx*8 + 2];
                o0.w = v[3] + bout[tx*8 + 3];
                o1.x = v[4] + bout[tx*8 + 4];
                o1.y = v[5] + bout[tx*8 + 5];
                o1.z = v[6] + bout[tx*8 + 6];
                o1.w = v[7] + bout[tx*8 + 7];
                *(float4*)(O1 + (size_t)row * N + tx*8)     = o0;
                *(float4*)(O1 + (size_t)row * N + tx*8 + 4) = o1;
            } else {
                float s = g_dinv[row];
                float4 o0, o1;
                o0.x = v[0]*s; o0.y = v[1]*s; o0.z = v[2]*s; o0.w = v[3]*s;
                o1.x = v[4]*s; o1.y = v[5]*s; o1.z = v[6]*s; o1.w = v[7]*s;
                *(float4*)(O1 + (size_t)row * N + tx*8)     = o0;
                *(float4*)(O1 + (size_t)row * N + tx*8 + 4) = o1;
                *(float4*)(O2 + (size_t)row * N + tx*8)     = o0;
                *(float4*)(O2 + (size_t)row * N + tx*8 + 4) = o1;
            }
        }
    }
}

// ---------------------------------------------------------------------------
extern "C" void kernel_launch(void* const* d_in, const int* in_sizes, int n_in,
                              void* d_out, int out_size) {
    const float* x   = (const float*)d_in[0];
    const void*  ei  = d_in[1];
    const float* W1  = (const float*)d_in[3];
    const float* b1  = (const float*)d_in[4];
    const float* W2  = (const float*)d_in[5];
    const float* b2  = (const float*)d_in[6];
    const float* Wfc = (const float*)d_in[7];
    const float* bfc = (const float*)d_in[8];
    float* out = (float*)d_out;

    int n = in_sizes[0] / 128;   // 100000
    int E = in_sizes[1] / 2;     // 1600000

    float *A, *B;
    cudaGetSymbolAddress((void**)&A, g_A);
    cudaGetSymbolAddress((void**)&B, g_B);

    int nb_n  = (n + 255) / 256;
    int nb_E  = (E + 255) / 256;
    int nb_sc = (E * 16 + 255) / 256;
    int nb_g64 = (n + 255) / 256;   // BM=256 for N=64
    int nb_g32 = (n + 511) / 512;   // BM=512 for N=32

    // Prep: dtype probe, edge convert + degree, dinv
    probe_dtype<<<1, 256>>>((const long long*)ei);
    init_deg<<<nb_n, 256>>>(n);
    convert_deg<<<nb_E, 256>>>(ei, E);
    dinv_kernel<<<nb_n, 256>>>(n);

    // Layer 1: A = B = dinv*(x@W1); B += scatter(A)
    gemm_f32x2<128, 64, false, false><<<nb_g64, 256>>>(x, W1, nullptr, nullptr, A, B, n);
    scatter_kernel<<<nb_sc, 256>>>(A, B, E);

    // Layer 2: X2 = relu(dinv*B + b1) on load; A = B = dinv*(X2@W2); B += scatter(A)
    gemm_f32x2<64, 64, true, false><<<nb_g64, 256>>>(B, W2, b1, nullptr, A, B, n);
    scatter_kernel<<<nb_sc, 256>>>(A, B, E);

    // FC: out = relu(dinv*B + b2) @ Wfc + bfc
    gemm_f32x2<64, 32, true, true><<<nb_g32, 256>>>(B, Wfc, b2, bfc, out, nullptr, n);
}

// round 8
// speedup vs baseline: 1.6032x; 1.6032x over previous
#include <cuda_runtime.h>
#include <cuda_bf16.h>
#include <math.h>

#define NMAX   100000
#define EMAX   1600000
#define FH     64

// Scratch (alloc-free rule: __device__ globals)
__device__ float g_A[NMAX * FH];      // gather source h'
__device__ float g_B[NMAX * FH];      // scatter accumulator
__device__ float g_deg[NMAX];
__device__ float g_dinv[NMAX];
__device__ int2  g_edges[EMAX];
__device__ int   g_is64;

// ---------------------------------------------------------------------------
// Detect int64 vs int32 edge_index (values < 100000 -> all int64 high words 0)
__global__ void probe_dtype(const long long* __restrict__ ei) {
    __shared__ int any;
    if (threadIdx.x == 0) any = 0;
    __syncthreads();
    for (int i = threadIdx.x; i < 1024; i += blockDim.x) {
        long long v = ei[i];
        if ((v >> 32) != 0) any = 1;
    }
    __syncthreads();
    if (threadIdx.x == 0) g_is64 = (any == 0) ? 1 : 0;
}

__global__ void init_deg(int n) {
    int i = blockIdx.x * blockDim.x + threadIdx.x;
    if (i < n) g_deg[i] = 1.0f;            // self-loop
}

// Convert edges to packed int2 + accumulate degree
__global__ void convert_deg(const void* __restrict__ ei, int E) {
    int e = blockIdx.x * blockDim.x + threadIdx.x;
    if (e >= E) return;
    int s, d;
    if (g_is64) {
        const long long* p = (const long long*)ei;
        s = (int)p[e]; d = (int)p[E + e];
    } else {
        const int* p = (const int*)ei;
        s = p[e]; d = p[E + e];
    }
    g_edges[e] = make_int2(s, d);
    atomicAdd(&g_deg[d], 1.0f);
}

__global__ void dinv_kernel(int n) {
    int i = blockIdx.x * blockDim.x + threadIdx.x;
    if (i < n) {
        float dg = g_deg[i];
        g_dinv[i] = (dg > 0.f) ? rsqrtf(dg) : 0.f;
    }
}

// ---------------------------------------------------------------------------
// Scatter: B[d,:] += A[s,:]  (normalization folded into A and consumer load).
// 16 lanes per edge, float4 RED.
__global__ void scatter_kernel(const float* __restrict__ A, float* __restrict__ B, int E) {
    int g = blockIdx.x * blockDim.x + threadIdx.x;
    int lane = g & 15;
    int e = g >> 4;
    if (e >= E) return;
    int2 ed = g_edges[e];
    float4 v = ((const float4*)(A + (size_t)ed.x * FH))[lane];
    atomicAdd(((float4*)(B + (size_t)ed.y * FH)) + lane, v);
}

// ---------------------------------------------------------------------------
// Tiled fp32 GEMM (R1 design): out = f(X) @ W, 64-row tiles, 4x4 thread tile.
// TRANS: x_load = relu(dinv[row]*x + bin[col])
// FC==0: epilogue v *= dinv[row], dual-write O1 (gather src) + O2 (accum init)
// FC==1: epilogue v += bout[col], write O1 only
template<int K, int N, bool TRANS, bool FC>
__global__ void gemm_kernel(const float* X, const float* __restrict__ W,
                            const float* __restrict__ bin, const float* __restrict__ bout,
                            float* __restrict__ O1, float* O2, int n) {
    constexpr int TX = N / 4;
    constexpr int NT = TX * 16;
    __shared__ float Xs[64][65];
    __shared__ float Ws[64][N];
    int row0 = blockIdx.x * 64;
    int tx = threadIdx.x, ty = threadIdx.y;
    int tid = ty * TX + tx;
    float acc[4][4] = {};

    for (int k0 = 0; k0 < K; k0 += 64) {
        // X tile: 64 rows x 64 cols (float4 loads, coalesced)
        for (int i = tid; i < 64 * 16; i += NT) {
            int r = i >> 4, c4 = i & 15;
            float4 v = make_float4(0.f, 0.f, 0.f, 0.f);
            int row = row0 + r;
            if (row < n) {
                v = *(const float4*)(X + (size_t)row * K + k0 + c4 * 4);
                if (TRANS) {
                    float s = g_dinv[row];
                    v.x = fmaxf(fmaf(v.x, s, bin[k0 + c4*4 + 0]), 0.f);
                    v.y = fmaxf(fmaf(v.y, s, bin[k0 + c4*4 + 1]), 0.f);
                    v.z = fmaxf(fmaf(v.z, s, bin[k0 + c4*4 + 2]), 0.f);
                    v.w = fmaxf(fmaf(v.w, s, bin[k0 + c4*4 + 3]), 0.f);
                }
            }
            Xs[r][c4 * 4 + 0] = v.x; Xs[r][c4 * 4 + 1] = v.y;
            Xs[r][c4 * 4 + 2] = v.z; Xs[r][c4 * 4 + 3] = v.w;
        }
        // W tile: 64 rows x N cols
        for (int i = tid; i < 64 * (N / 4); i += NT) {
            int r = i / (N / 4), c4 = i % (N / 4);
            float4 v = *(const float4*)(W + (size_t)(k0 + r) * N + c4 * 4);
            *(float4*)&Ws[r][c4 * 4] = v;
        }
        __syncthreads();
        #pragma unroll
        for (int k = 0; k < 64; k++) {
            float4 w = *(float4*)&Ws[k][tx * 4];
            #pragma unroll
            for (int i = 0; i < 4; i++) {
                float a = Xs[ty * 4 + i][k];
                acc[i][0] += a * w.x;
                acc[i][1] += a * w.y;
                acc[i][2] += a * w.z;
                acc[i][3] += a * w.w;
            }
        }
        __syncthreads();
    }

    #pragma unroll
    for (int i = 0; i < 4; i++) {
        int row = row0 + ty * 4 + i;
        if (row >= n) continue;
        if (FC) {
            float4 o;
            o.x = acc[i][0] + bout[tx*4 + 0];
            o.y = acc[i][1] + bout[tx*4 + 1];
            o.z = acc[i][2] + bout[tx*4 + 2];
            o.w = acc[i][3] + bout[tx*4 + 3];
            *(float4*)(O1 + (size_t)row * N + tx * 4) = o;
        } else {
            float s = g_dinv[row];
            float4 o;
            o.x = acc[i][0] * s;
            o.y = acc[i][1] * s;
            o.z = acc[i][2] * s;
            o.w = acc[i][3] * s;
            *(float4*)(O1 + (size_t)row * N + tx * 4) = o;
            *(float4*)(O2 + (size_t)row * N + tx * 4) = o;
        }
    }
}

// ---------------------------------------------------------------------------
extern "C" void kernel_launch(void* const* d_in, const int* in_sizes, int n_in,
                              void* d_out, int out_size) {
    const float* x   = (const float*)d_in[0];
    const void*  ei  = d_in[1];
    const float* W1  = (const float*)d_in[3];
    const float* b1  = (const float*)d_in[4];
    const float* W2  = (const float*)d_in[5];
    const float* b2  = (const float*)d_in[6];
    const float* Wfc = (const float*)d_in[7];
    const float* bfc = (const float*)d_in[8];
    float* out = (float*)d_out;

    int n = in_sizes[0] / 128;   // 100000
    int E = in_sizes[1] / 2;     // 1600000

    float *A, *B;
    cudaGetSymbolAddress((void**)&A, g_A);
    cudaGetSymbolAddress((void**)&B, g_B);

    int nb_n  = (n + 255) / 256;
    int nb_E  = (E + 255) / 256;
    int nb_sc = (E * 16 + 255) / 256;
    int nb_g  = (n + 63) / 64;

    // Prep: dtype probe, edge convert + degree, dinv
    probe_dtype<<<1, 256>>>((const long long*)ei);
    init_deg<<<nb_n, 256>>>(n);
    convert_deg<<<nb_E, 256>>>(ei, E);
    dinv_kernel<<<nb_n, 256>>>(n);

    // Layer 1: A = B = dinv*(x@W1); B += scatter(A)
    gemm_kernel<128, 64, false, false><<<nb_g, dim3(16, 16)>>>(x, W1, nullptr, nullptr, A, B, n);
    scatter_kernel<<<nb_sc, 256>>>(A, B, E);

    // Layer 2: X2 = relu(dinv*B + b1) on load; A = B = dinv*(X2@W2); B += scatter(A)
    gemm_kernel<64, 64, true, false><<<nb_g, dim3(16, 16)>>>(B, W2, b1, nullptr, A, B, n);
    scatter_kernel<<<nb_sc, 256>>>(A, B, E);

    // FC: out = relu(dinv*B + b2) @ Wfc + bfc
    gemm_kernel<64, 32, true, true><<<nb_g, dim3(8, 16)>>>(B, Wfc, b2, bfc, out, nullptr, n);
}